// round 2
// baseline (speedup 1.0000x reference)
#include <cuda_runtime.h>

#define BATCH 8
#define CH    64
#define HH    256
#define WW    256
#define KW    3
#define TW    16
#define NT    (WW / TW)          // 16 tiles along W
#define NCTA  (BATCH * NT)       // 128 CTAs, one wave
#define NTHR  128                // 64 co x 2 w-segments

typedef unsigned long long u64;

__device__ int g_progress[NCTA];

// ---- packed f32x2 FMA (Blackwell) ------------------------------------------
__device__ __forceinline__ u64 fma2(u64 a, u64 b, u64 c) {
    u64 d;
    asm("fma.rn.f32x2 %0, %1, %2, %3;" : "=l"(d) : "l"(a), "l"(b), "l"(c));
    return d;
}
__device__ __forceinline__ void unpack2(u64 v, float& lo, float& hi) {
    unsigned a, b;
    asm("mov.b64 {%0,%1}, %2;" : "=r"(a), "=r"(b) : "l"(v));
    lo = __uint_as_float(a);
    hi = __uint_as_float(b);
}

// ---- release/acquire flag ops ----------------------------------------------
__device__ __forceinline__ int ld_acq(const int* p) {
    int v;
    asm volatile("ld.acquire.gpu.global.b32 %0, [%1];" : "=r"(v) : "l"(p));
    return v;
}
__device__ __forceinline__ void st_rel(int* p, int v) {
    asm volatile("st.release.gpu.global.b32 [%0], %1;" :: "l"(p), "r"(v) : "memory");
}

// ---- shared memory layout ---------------------------------------------------
struct SM {
    float2 wsp[CH][CH][KW];        // pre-splatted weights {w,w}  (96 KB)
    float2 pp[2][CH][TW + 1];      // pair array: pp[buf][ci][j] = (v[j-1], v[j])
    float  shL[CH];                // left halo column (row h-1)
    float  shR[CH];                // right halo column (row h-1)
};

__global__ void reset_kernel() {
    if (threadIdx.x < NCTA) g_progress[threadIdx.x] = -1;
}

__global__ void __launch_bounds__(NTHR, 1)
spatial_kernel(const float* __restrict__ X, const float* __restrict__ Wc,
               const float* __restrict__ bc, float* __restrict__ out) {
    extern __shared__ char smraw[];
    SM* sm = reinterpret_cast<SM*>(smraw);

    const int bid = blockIdx.x;
    const int b   = bid / NT;
    const int t   = bid % NT;
    const int w0  = t * TW;
    const int tid = threadIdx.x;
    const int co  = tid >> 1;          // output channel owned by this thread
    const int ws  = tid & 1;           // which 8-wide segment of the tile
    const int wb  = ws * 8;

    // ---- one-time: load + splat weights into shared ----
    for (int idx = tid; idx < CH * CH * KW; idx += NTHR) {
        float v = Wc[idx];             // layout [co][ci][k] row-major
        reinterpret_cast<float2*>(sm->wsp)[idx] = make_float2(v, v);
    }
    // permanently-zero halo slots (handled via correction path instead)
    if (tid < CH) {
        sm->pp[0][tid][0].x  = 0.f;  sm->pp[1][tid][0].x  = 0.f;
        sm->pp[0][tid][TW].y = 0.f;  sm->pp[1][tid][TW].y = 0.f;
    }
    const float bias = bc[co];

    // ---- step 0: Y[0] = X[0] ----
    const size_t rowbase0 = ((size_t)(b * CH + co) * HH + 0) * WW + w0 + wb;
    float4 x0 = *reinterpret_cast<const float4*>(X + rowbase0);
    float4 x1 = *reinterpret_cast<const float4*>(X + rowbase0 + 4);
    float y[8] = {x0.x, x0.y, x0.z, x0.w, x1.x, x1.y, x1.z, x1.w};
    *reinterpret_cast<float4*>(out + rowbase0)     = x0;
    *reinterpret_cast<float4*>(out + rowbase0 + 4) = x1;

    int cur = 0;
#pragma unroll
    for (int i = 0; i < 8; i++) {
        sm->pp[cur][co][wb + i].y     = y[i];
        sm->pp[cur][co][wb + i + 1].x = y[i];
    }
    __threadfence();
    __syncthreads();
    if (tid == 0) st_rel(&g_progress[bid], 0);

    // ---- recurrence over rows ----
    for (int h = 1; h < HH; h++) {
        // spin for neighbors' row h-1 (expected near-zero wait in lockstep)
        if (tid == 0 && t > 0) {
            while (ld_acq(&g_progress[bid - 1]) < h - 1) __nanosleep(40);
        }
        if (tid == 64 && t < NT - 1) {
            while (ld_acq(&g_progress[bid + 1]) < h - 1) __nanosleep(40);
        }
        __syncthreads();   // S1: spin done; pp[cur] writes from prev step visible

        // issue long-latency loads now; consumed after the conv loop
        float vH = 0.f;
        if (tid < CH) {
            if (t > 0)
                vH = __ldcg(out + ((size_t)(b * CH + tid) * HH + (h - 1)) * WW + (w0 - 1));
        } else {
            if (t < NT - 1)
                vH = __ldcg(out + ((size_t)(b * CH + tid - CH) * HH + (h - 1)) * WW + (w0 + TW));
        }
        const size_t rowbase = ((size_t)(b * CH + co) * HH + h) * WW + w0 + wb;
        x0 = *reinterpret_cast<const float4*>(X + rowbase);
        x1 = *reinterpret_cast<const float4*>(X + rowbase + 4);

        // ---- main conv: 64 ci, 8 outputs/thread as 4 packed f32x2 accs ----
        u64 a0 = 0ull, a1 = 0ull, a2 = 0ull, a3 = 0ull;
        const u64* wrow = reinterpret_cast<const u64*>(&sm->wsp[co][0][0]);
        const u64* prow = reinterpret_cast<const u64*>(&sm->pp[cur][0][wb]);
#pragma unroll 4
        for (int ci = 0; ci < CH; ci++) {
            u64 wk0 = wrow[ci * 3 + 0];
            u64 wk1 = wrow[ci * 3 + 1];
            u64 wk2 = wrow[ci * 3 + 2];
            const u64* p = prow + ci * (TW + 1);
            u64 p0 = p[0], p1 = p[1], p2 = p[2], p3 = p[3], p4 = p[4];
            u64 p5 = p[5], p6 = p[6], p7 = p[7], p8 = p[8];
            a0 = fma2(wk0, p0, a0); a0 = fma2(wk1, p1, a0); a0 = fma2(wk2, p2, a0);
            a1 = fma2(wk0, p2, a1); a1 = fma2(wk1, p3, a1); a1 = fma2(wk2, p4, a1);
            a2 = fma2(wk0, p4, a2); a2 = fma2(wk1, p5, a2); a2 = fma2(wk2, p6, a2);
            a3 = fma2(wk0, p6, a3); a3 = fma2(wk1, p7, a3); a3 = fma2(wk2, p8, a3);
        }

        // share halo columns
        if (tid < CH) sm->shL[tid] = vH; else sm->shR[tid - CH] = vH;
        __syncthreads();   // S2

        // halo corrections: only output w=0 (k=0 term) / w=15 (k=2 term)
        float corr = 0.f;
        {
            const float* sv = ws ? sm->shR : sm->shL;
            const float* wv = ws ? &sm->wsp[co][0][2].x : &sm->wsp[co][0][0].x;
#pragma unroll 8
            for (int ci = 0; ci < CH; ci++)
                corr += wv[ci * 6] * sv[ci];   // stride 3 float2 = 6 floats
        }

        float s[8];
        unpack2(a0, s[0], s[1]); unpack2(a1, s[2], s[3]);
        unpack2(a2, s[4], s[5]); unpack2(a3, s[6], s[7]);
        if (ws == 0) s[0] += corr; else s[7] += corr;

        float xr[8] = {x0.x, x0.y, x0.z, x0.w, x1.x, x1.y, x1.z, x1.w};
#pragma unroll
        for (int i = 0; i < 8; i++)
            y[i] = xr[i] + tanhf(s[i] + bias);

        *reinterpret_cast<float4*>(out + rowbase)     = make_float4(y[0], y[1], y[2], y[3]);
        *reinterpret_cast<float4*>(out + rowbase + 4) = make_float4(y[4], y[5], y[6], y[7]);

        const int nxt = cur ^ 1;
#pragma unroll
        for (int i = 0; i < 8; i++) {
            sm->pp[nxt][co][wb + i].y     = y[i];
            sm->pp[nxt][co][wb + i + 1].x = y[i];
        }
        __threadfence();
        __syncthreads();   // S3: all threads' STG fenced before publish
        if (tid == 0) st_rel(&g_progress[bid], h);
        cur = nxt;
    }
}

extern "C" void kernel_launch(void* const* d_in, const int* in_sizes, int n_in,
                              void* d_out, int out_size) {
    const float* X  = (const float*)d_in[0];
    const float* Wc = (const float*)d_in[1];
    const float* bc = (const float*)d_in[2];
    float* out = (float*)d_out;

    cudaFuncSetAttribute(spatial_kernel,
                         cudaFuncAttributeMaxDynamicSharedMemorySize,
                         (int)sizeof(SM));

    reset_kernel<<<1, NCTA>>>();
    spatial_kernel<<<NCTA, NTHR, sizeof(SM)>>>(X, Wc, bc, out);
}

// round 3
// speedup vs baseline: 1.5966x; 1.5966x over previous
#include <cuda_runtime.h>

#define BATCH 8
#define CH    64
#define HH    256
#define WW    256
#define TW    16
#define NT    (WW / TW)          // 16 tiles along W
#define NCTA  (BATCH * NT)       // 128 CTAs, one wave
#define NTHR  512                // 64 co x 2 ws x 4 ci-groups
#define CIPT  16                 // ci per thread
#define PSTR  (TW + 2)           // pp row stride in float2 (pad for 16B align)

typedef unsigned long long u64;

__device__ int g_progress[NCTA];

union F4U { float4 f; u64 u[2]; };
union F2U { float2 f; u64 u; };

// ---- packed f32x2 ops ------------------------------------------------------
static __device__ __forceinline__ u64 fma2(u64 a, u64 b, u64 c) {
    u64 d;
    asm("fma.rn.f32x2 %0, %1, %2, %3;" : "=l"(d) : "l"(a), "l"(b), "l"(c));
    return d;
}
static __device__ __forceinline__ u64 add2(u64 a, u64 b) {
    u64 d;
    asm("add.rn.f32x2 %0, %1, %2;" : "=l"(d) : "l"(a), "l"(b));
    return d;
}
static __device__ __forceinline__ u64 splat2(float x) {
    u64 r;
    asm("mov.b64 %0, {%1, %1};" : "=l"(r) : "f"(x));
    return r;
}
static __device__ __forceinline__ u64 pack2(float lo, float hi) {
    u64 r;
    asm("mov.b64 %0, {%1, %2};" : "=l"(r) : "f"(lo), "f"(hi));
    return r;
}
static __device__ __forceinline__ void unpack2(u64 v, float& lo, float& hi) {
    unsigned a, b;
    asm("mov.b64 {%0,%1}, %2;" : "=r"(a), "=r"(b) : "l"(v));
    lo = __uint_as_float(a);
    hi = __uint_as_float(b);
}

// ---- release/acquire flag ops ----------------------------------------------
static __device__ __forceinline__ int ld_acq(const int* p) {
    int v;
    asm volatile("ld.acquire.gpu.global.b32 %0, [%1];" : "=r"(v) : "l"(p));
    return v;
}
static __device__ __forceinline__ void st_rel(int* p, int v) {
    asm volatile("st.release.gpu.global.b32 [%0], %1;" :: "l"(p), "r"(v) : "memory");
}

// ---- fast tanh (abs err ~1e-7) ---------------------------------------------
static __device__ __forceinline__ float ftanh(float x) {
    float e = __expf(2.0f * x);
    return 1.0f - __fdividef(2.0f, e + 1.0f);
}

// publish one row segment into the pair array: row[m] = (y[m-1], y[m])
static __device__ __forceinline__ void publish_row(float2* row, int ws, const float y[8]) {
    if (ws == 0) {
        row[0] = make_float2(0.f, y[0]);         // left halo slot stays 0
#pragma unroll
        for (int i = 1; i < 8; i++) row[i] = make_float2(y[i - 1], y[i]);
        row[8].x = y[7];
    } else {
        row[8].y = y[0];
#pragma unroll
        for (int i = 1; i < 8; i++) row[8 + i] = make_float2(y[i - 1], y[i]);
        row[16] = make_float2(y[7], 0.f);        // right halo slot stays 0
    }
}

__global__ void reset_kernel() {
    if (threadIdx.x < NCTA) g_progress[threadIdx.x] = -1;
}

__global__ void __launch_bounds__(NTHR, 1)
spatial_kernel(const float* __restrict__ X, const float* __restrict__ Wc,
               const float* __restrict__ bc, float* __restrict__ out) {
    __shared__ float2 pp[2][CH][PSTR];     // pair rows, double buffered (18 KB)
    __shared__ u64    red[3][128][4];      // partial sums from cig 1..3 (12 KB)
    __shared__ float  shL[CH], shR[CH];    // halo columns

    const int tid = threadIdx.x;
    const int cig = tid >> 7;              // 0..3  ci-group
    const int wt  = tid & 127;
    const int co  = wt >> 1;               // output channel
    const int ws  = wt & 1;                // 8-wide segment
    const int wb  = ws * 8;

    const int bid = blockIdx.x;
    const int b   = bid / NT;
    const int t   = bid % NT;
    const int w0  = t * TW;

    // ---- one-time: this thread's 16 ci x 3 weights into registers ----
    float wr[CIPT * 3];
    {
        const float4* wp = reinterpret_cast<const float4*>(
            Wc + ((size_t)co * CH + cig * CIPT) * 3);
#pragma unroll
        for (int i = 0; i < 12; i++) {
            float4 v = wp[i];
            wr[i * 4 + 0] = v.x; wr[i * 4 + 1] = v.y;
            wr[i * 4 + 2] = v.z; wr[i * 4 + 3] = v.w;
        }
    }
    const float bias = bc[co];

    // ---- step 0: Y[0] = X[0] ----
    int cur = 0;
    if (cig == 0) {
        const size_t rb0 = ((size_t)(b * CH + co) * HH + 0) * WW + w0 + wb;
        float4 x0 = *reinterpret_cast<const float4*>(X + rb0);
        float4 x1 = *reinterpret_cast<const float4*>(X + rb0 + 4);
        *reinterpret_cast<float4*>(out + rb0)     = x0;
        *reinterpret_cast<float4*>(out + rb0 + 4) = x1;
        float y[8] = {x0.x, x0.y, x0.z, x0.w, x1.x, x1.y, x1.z, x1.w};
        publish_row(pp[0][co], ws, y);
    }
    __threadfence();
    __syncthreads();
    if (tid == 0) st_rel(&g_progress[bid], 0);

    // ---- recurrence over rows ----
    for (int h = 1; h < HH; h++) {
        if (tid == 0 && t > 0)
            while (ld_acq(&g_progress[bid - 1]) < h - 1) __nanosleep(32);
        if (tid == 64 && t < NT - 1)
            while (ld_acq(&g_progress[bid + 1]) < h - 1) __nanosleep(32);
        __syncthreads();   // S1

        // halo loads (cig1), consumed after conv; latency hidden behind conv
        float vH = 0.f;
        if (cig == 1) {
            if (wt < CH) {
                if (t > 0)
                    vH = __ldcg(out + ((size_t)(b * CH + wt) * HH + (h - 1)) * WW + (w0 - 1));
            } else {
                if (t < NT - 1)
                    vH = __ldcg(out + ((size_t)(b * CH + wt - CH) * HH + (h - 1)) * WW + (w0 + TW));
            }
        }

        // X loads (cig0), consumed in epilogue
        const size_t rb = ((size_t)(b * CH + co) * HH + h) * WW + w0 + wb;
        float4 x0, x1;
        if (cig == 0) {
            x0 = *reinterpret_cast<const float4*>(X + rb);
            x1 = *reinterpret_cast<const float4*>(X + rb + 4);
        }

        // ---- main conv over this thread's 16 ci ----
        u64 a0 = 0ull, a1 = 0ull, a2 = 0ull, a3 = 0ull;
        {
            const char* base = reinterpret_cast<const char*>(&pp[cur][cig * CIPT][0]) + wb * 8;
#pragma unroll
            for (int j = 0; j < CIPT; j++) {
                const float4* p4 = reinterpret_cast<const float4*>(base + j * (PSTR * 8));
                F4U q0, q1, q2, q3; F2U q4;
                q0.f = p4[0]; q1.f = p4[1]; q2.f = p4[2]; q3.f = p4[3];
                q4.f = *reinterpret_cast<const float2*>(p4 + 4);
                u64 wk0 = splat2(wr[j * 3 + 0]);
                u64 wk1 = splat2(wr[j * 3 + 1]);
                u64 wk2 = splat2(wr[j * 3 + 2]);
                a0 = fma2(wk0, q0.u[0], a0);
                a0 = fma2(wk1, q0.u[1], a0);
                a0 = fma2(wk2, q1.u[0], a0);
                a1 = fma2(wk0, q1.u[0], a1);
                a1 = fma2(wk1, q1.u[1], a1);
                a1 = fma2(wk2, q2.u[0], a1);
                a2 = fma2(wk0, q2.u[0], a2);
                a2 = fma2(wk1, q2.u[1], a2);
                a2 = fma2(wk2, q3.u[0], a2);
                a3 = fma2(wk0, q3.u[0], a3);
                a3 = fma2(wk1, q3.u[1], a3);
                a3 = fma2(wk2, q4.u,    a3);
            }
        }

        if (cig == 1) {
            if (wt < CH) shL[wt] = vH; else shR[wt - CH] = vH;
        }
        __syncthreads();   // S2: halo columns visible

        // halo correction: each thread covers its own 16 ci with register weights
        {
            float c = 0.f;
            const float4* sv4 = reinterpret_cast<const float4*>(
                (ws ? shR : shL) + cig * CIPT);
#pragma unroll
            for (int g = 0; g < 4; g++) {
                float4 s = sv4[g];
                float wA0 = wr[(g * 4 + 0) * 3], wA2 = wr[(g * 4 + 0) * 3 + 2];
                float wB0 = wr[(g * 4 + 1) * 3], wB2 = wr[(g * 4 + 1) * 3 + 2];
                float wC0 = wr[(g * 4 + 2) * 3], wC2 = wr[(g * 4 + 2) * 3 + 2];
                float wD0 = wr[(g * 4 + 3) * 3], wD2 = wr[(g * 4 + 3) * 3 + 2];
                c += (ws ? wA2 : wA0) * s.x;
                c += (ws ? wB2 : wB0) * s.y;
                c += (ws ? wC2 : wC0) * s.z;
                c += (ws ? wD2 : wD0) * s.w;
            }
            if (ws == 0) a0 = add2(a0, pack2(c, 0.f));
            else         a3 = add2(a3, pack2(0.f, c));
        }

        if (cig > 0) {
            u64* r = red[cig - 1][wt];
            r[0] = a0; r[1] = a1; r[2] = a2; r[3] = a3;
        }
        __syncthreads();   // S2b: partials visible

        if (cig == 0) {
#pragma unroll
            for (int cc = 0; cc < 3; cc++) {
                const u64* r = red[cc][wt];
                a0 = add2(a0, r[0]); a1 = add2(a1, r[1]);
                a2 = add2(a2, r[2]); a3 = add2(a3, r[3]);
            }
            float s[8];
            unpack2(a0, s[0], s[1]); unpack2(a1, s[2], s[3]);
            unpack2(a2, s[4], s[5]); unpack2(a3, s[6], s[7]);
            float xr[8] = {x0.x, x0.y, x0.z, x0.w, x1.x, x1.y, x1.z, x1.w};
            float y[8];
#pragma unroll
            for (int i = 0; i < 8; i++)
                y[i] = xr[i] + ftanh(s[i] + bias);
            *reinterpret_cast<float4*>(out + rb)     = make_float4(y[0], y[1], y[2], y[3]);
            *reinterpret_cast<float4*>(out + rb + 4) = make_float4(y[4], y[5], y[6], y[7]);
            publish_row(pp[cur ^ 1][co], ws, y);
            __threadfence();
        }
        __syncthreads();   // S3
        if (tid == 0) st_rel(&g_progress[bid], h);
        cur ^= 1;
    }
}

extern "C" void kernel_launch(void* const* d_in, const int* in_sizes, int n_in,
                              void* d_out, int out_size) {
    const float* X  = (const float*)d_in[0];
    const float* Wc = (const float*)d_in[1];
    const float* bc = (const float*)d_in[2];
    float* out = (float*)d_out;

    reset_kernel<<<1, NCTA>>>();
    spatial_kernel<<<NCTA, NTHR>>>(X, Wc, bc, out);
}

// round 4
// speedup vs baseline: 2.1232x; 1.3298x over previous
#include <cuda_runtime.h>

#define BATCH 8
#define CH    64
#define HH    256
#define WW    256
#define TW    16
#define NT    (WW / TW)          // 16 tiles along W
#define NCTA  (BATCH * NT)       // 128 CTAs, one wave
#define NTHR  512                // 64 co x 2 ws x 4 ci-groups
#define CIPT  16                 // ci per thread
#define PSTR  18                 // pp row stride in float2 (16B-aligned: 144B)

typedef unsigned long long u64;

__device__ int   g_progress[NCTA];
__device__ float g_halo[2][NCTA][2][CH];   // [parity][cta][left/right edge][ch]

union F4U { float4 f; u64 u[2]; };
union F2U { float2 f; u64 u; };

// ---- packed f32x2 ops ------------------------------------------------------
static __device__ __forceinline__ u64 fma2(u64 a, u64 b, u64 c) {
    u64 d;
    asm("fma.rn.f32x2 %0, %1, %2, %3;" : "=l"(d) : "l"(a), "l"(b), "l"(c));
    return d;
}
static __device__ __forceinline__ u64 add2(u64 a, u64 b) {
    u64 d;
    asm("add.rn.f32x2 %0, %1, %2;" : "=l"(d) : "l"(a), "l"(b));
    return d;
}
static __device__ __forceinline__ u64 splat2(float x) {
    u64 r;
    asm("mov.b64 %0, {%1, %1};" : "=l"(r) : "f"(x));
    return r;
}
static __device__ __forceinline__ void unpack2(u64 v, float& lo, float& hi) {
    unsigned a, b;
    asm("mov.b64 {%0,%1}, %2;" : "=r"(a), "=r"(b) : "l"(v));
    lo = __uint_as_float(a);
    hi = __uint_as_float(b);
}

// ---- release/acquire flag ops ----------------------------------------------
static __device__ __forceinline__ int ld_acq(const int* p) {
    int v;
    asm volatile("ld.acquire.gpu.global.b32 %0, [%1];" : "=r"(v) : "l"(p));
    return v;
}
static __device__ __forceinline__ void st_rel(int* p, int v) {
    asm volatile("st.release.gpu.global.b32 [%0], %1;" :: "l"(p), "r"(v) : "memory");
}

// ---- fast tanh (abs err ~1e-7) ---------------------------------------------
static __device__ __forceinline__ float ftanh(float x) {
    float e = __expf(2.0f * x);
    return 1.0f - __fdividef(2.0f, e + 1.0f);
}

__global__ void reset_kernel() {
    if (threadIdx.x < NCTA) g_progress[threadIdx.x] = -1;
}

__global__ void __launch_bounds__(NTHR, 1)
spatial_kernel(const float* __restrict__ X, const float* __restrict__ Wc,
               const float* __restrict__ bc, float* __restrict__ out) {
    __shared__ float2 pp[2][CH][PSTR];          // pair rows, double buffered (18 KB)
    __shared__ u64    redA[4][128], redB[4][128], redC[4][128], redD[4][128]; // 16 KB
    __shared__ float  shL[CH], shR[CH];         // neighbor halo columns (row h-1)

    const int tid = threadIdx.x;
    const int cig = tid >> 7;              // 0..3  ci-group
    const int wt  = tid & 127;
    const int co  = wt >> 1;               // output channel
    const int ws  = wt & 1;                // 8-wide segment
    const int wb  = ws * 8;
    const int o0  = wb + cig * 2;          // this thread's two output columns
    const int bid = blockIdx.x;
    const int b   = bid / NT;
    const int t   = bid % NT;
    const int w0  = t * TW;

    // ---- one-time: this thread's 16 ci x 3 weights into registers ----
    float wr[CIPT * 3];
    {
        const float4* wp = reinterpret_cast<const float4*>(
            Wc + ((size_t)co * CH + cig * CIPT) * 3);
#pragma unroll
        for (int i = 0; i < 12; i++) {
            float4 v = wp[i];
            wr[i * 4 + 0] = v.x; wr[i * 4 + 1] = v.y;
            wr[i * 4 + 2] = v.z; wr[i * 4 + 3] = v.w;
        }
    }
    const float bias = bc[co];

    // permanent zero halo slots in both pair buffers
    if (tid < CH) {
        pp[0][tid][0].x  = 0.f;  pp[1][tid][0].x  = 0.f;
        pp[0][tid][16].y = 0.f;  pp[1][tid][16].y = 0.f;
    }

    // ---- step 0: Y[0] = X[0], distributed across all 512 threads ----
    const size_t rowstr = (size_t)WW;
    const size_t chanbase = ((size_t)(b * CH + co) * HH) * WW + w0;
    {
        float2 x2 = *reinterpret_cast<const float2*>(X + chanbase + o0);
        *reinterpret_cast<float2*>(out + chanbase + o0) = x2;
        pp[0][co][o0].y     = x2.x;
        pp[0][co][o0 + 1].x = x2.x;
        pp[0][co][o0 + 1].y = x2.y;
        pp[0][co][o0 + 2].x = x2.y;
        if (ws == 0 && cig == 0) g_halo[0][bid][0][co] = x2.x;   // w=0
        if (ws == 1 && cig == 3) g_halo[0][bid][1][co] = x2.y;   // w=15
    }
    __syncthreads();
    if (tid == 0) st_rel(&g_progress[bid], 0);

    int cur = 0;
    // ---- recurrence over rows ----
    for (int h = 1; h < HH; h++) {
        const int par = (h - 1) & 1;
        // hard spin for neighbors' row h-1 (two spinner threads, no sleep)
        if (tid == 0 && t > 0)
            while (ld_acq(&g_progress[bid - 1]) < h - 1) { }
        if (tid == 256 && t < NT - 1)
            while (ld_acq(&g_progress[bid + 1]) < h - 1) { }
        __syncthreads();   // S1

        // cig1: fetch neighbor halo columns (coalesced) and park in smem.
        if (cig == 1) {
            float v = 0.f;
            if (wt < CH) {
                if (t > 0) v = __ldcg(&g_halo[par][bid - 1][1][wt]);
                shL[wt] = v;
            } else {
                if (t < NT - 1) v = __ldcg(&g_halo[par][bid + 1][0][wt - CH]);
                shR[wt - CH] = v;
            }
        }
        // every thread: X for its own two outputs (consumed in epilogue)
        const size_t rb = chanbase + (size_t)h * rowstr;
        float2 x2 = *reinterpret_cast<const float2*>(X + rb + o0);

        // ---- main conv over this thread's 16 ci ----
        u64 a0 = 0ull, a1 = 0ull, a2 = 0ull, a3 = 0ull;
        {
            const char* base = reinterpret_cast<const char*>(&pp[cur][cig * CIPT][0]) + wb * 8;
#pragma unroll
            for (int j = 0; j < CIPT; j++) {
                const float4* p4 = reinterpret_cast<const float4*>(base + j * (PSTR * 8));
                F4U q0, q1, q2, q3; F2U q4;
                q0.f = p4[0]; q1.f = p4[1]; q2.f = p4[2]; q3.f = p4[3];
                q4.f = *reinterpret_cast<const float2*>(p4 + 4);
                u64 wk0 = splat2(wr[j * 3 + 0]);
                u64 wk1 = splat2(wr[j * 3 + 1]);
                u64 wk2 = splat2(wr[j * 3 + 2]);
                a0 = fma2(wk0, q0.u[0], a0);
                a0 = fma2(wk1, q0.u[1], a0);
                a0 = fma2(wk2, q1.u[0], a0);
                a1 = fma2(wk0, q1.u[0], a1);
                a1 = fma2(wk1, q1.u[1], a1);
                a1 = fma2(wk2, q2.u[0], a1);
                a2 = fma2(wk0, q2.u[0], a2);
                a2 = fma2(wk1, q2.u[1], a2);
                a2 = fma2(wk2, q3.u[0], a2);
                a3 = fma2(wk0, q3.u[0], a3);
                a3 = fma2(wk1, q3.u[1], a3);
                a3 = fma2(wk2, q4.u,    a3);
            }
        }
        __syncthreads();   // S2: shL/shR visible

        // halo correction over this thread's 16 ci (register weights)
        {
            float c = 0.f;
            const float4* sv4 = reinterpret_cast<const float4*>(
                (ws ? shR : shL) + cig * CIPT);
#pragma unroll
            for (int g = 0; g < 4; g++) {
                float4 s = sv4[g];
                c += (ws ? wr[(g*4+0)*3+2] : wr[(g*4+0)*3]) * s.x;
                c += (ws ? wr[(g*4+1)*3+2] : wr[(g*4+1)*3]) * s.y;
                c += (ws ? wr[(g*4+2)*3+2] : wr[(g*4+2)*3]) * s.z;
                c += (ws ? wr[(g*4+3)*3+2] : wr[(g*4+3)*3]) * s.w;
            }
            float lo, hi;
            if (ws == 0) { unpack2(a0, lo, hi); lo += c; a0 = 0; asm("mov.b64 %0,{%1,%2};":"=l"(a0):"f"(lo),"f"(hi)); }
            else         { unpack2(a3, lo, hi); hi += c; a3 = 0; asm("mov.b64 %0,{%1,%2};":"=l"(a3):"f"(lo),"f"(hi)); }
        }

        redA[cig][wt] = a0; redB[cig][wt] = a1;
        redC[cig][wt] = a2; redD[cig][wt] = a3;
        __syncthreads();   // S3: partials visible

        // ---- distributed epilogue: each thread finishes its 2 outputs ----
        {
            const u64* r = (cig == 0) ? &redA[0][wt] : (cig == 1) ? &redB[0][wt]
                         : (cig == 2) ? &redC[0][wt] : &redD[0][wt];
            u64 s2 = add2(add2(r[0], r[128]), add2(r[256], r[384]));
            float s_lo, s_hi;
            unpack2(s2, s_lo, s_hi);
            float y0 = x2.x + ftanh(s_lo + bias);
            float y1 = x2.y + ftanh(s_hi + bias);
            *reinterpret_cast<float2*>(out + rb + o0) = make_float2(y0, y1);
            float2* row = pp[cur ^ 1][co];
            row[o0].y     = y0;
            row[o0 + 1].x = y0;
            row[o0 + 1].y = y1;
            row[o0 + 2].x = y1;
            if (ws == 0 && cig == 0) g_halo[h & 1][bid][0][co] = y0;  // w=0
            if (ws == 1 && cig == 3) g_halo[h & 1][bid][1][co] = y1;  // w=15
        }
        __syncthreads();   // S4: all publishes done
        if (tid == 0) st_rel(&g_progress[bid], h);
        cur ^= 1;
    }
}

extern "C" void kernel_launch(void* const* d_in, const int* in_sizes, int n_in,
                              void* d_out, int out_size) {
    const float* X  = (const float*)d_in[0];
    const float* Wc = (const float*)d_in[1];
    const float* bc = (const float*)d_in[2];
    float* out = (float*)d_out;

    reset_kernel<<<1, NCTA>>>();
    spatial_kernel<<<NCTA, NTHR>>>(X, Wc, bc, out);
}